// round 1
// baseline (speedup 1.0000x reference)
#include <cuda_runtime.h>
#include <cstdint>
#include <math.h>

#define NN 8746
#define KD 8746
#define HD 32
#define ZD 16
#define TT 6
#define EE 100000

// GEMM tiling
#define BM 128
#define BK 32
#define KSPLIT 10
#define KCHUNK 896           // 28 k-tiles of 32; 10*896=8960 >= 8746
#define XS_STR 36            // padded row stride (floats), 16B aligned, conflict-free A loads
#define WS_STR 40            // padded row stride (floats), conflict-free B loads

// ---------------- scratch (device globals; no allocations allowed) ----------
__device__ float d_h0[NN * HD];          // x @ W1
__device__ int   d_cnt[TT * NN];         // per-(t, dst) edge counts
__device__ int   d_off[TT * (NN + 1)];   // CSR offsets
__device__ int   d_cur[TT * NN];         // scatter cursors
__device__ int   d_srcb[TT * EE];        // CSR: source node
__device__ int   d_eidb[TT * EE];        // CSR: original edge index (dedup tiebreak)
__device__ float d_wb[TT * EE];          // CSR: edge weight (losers zeroed)
__device__ float d_diag[TT * NN];        // implicit diagonal value (1 or 0 if self-edge won)
__device__ float d_dinv[TT * NN];        // colsum^-0.5
__device__ float d_g[TT * NN * ZD];      // h @ W2
__device__ int   d_i64;                  // ei dtype flag (1 = int64)

// ---------------- helpers ---------------------------------------------------
__device__ __forceinline__ void cp8(uint32_t dst, const void* src, int nb) {
    asm volatile("cp.async.ca.shared.global [%0], [%1], 8, %2;\n"
                 :: "r"(dst), "l"(src), "r"(nb) : "memory");
}
__device__ __forceinline__ uint32_t f2tf(float f) {
    uint32_t r;
    asm("cvt.rna.tf32.f32 %0, %1;" : "=r"(r) : "f"(f));
    return r;
}
__device__ __forceinline__ int ld_idx(const int* ei, int pos, int f) {
    // int64 little-endian: low word at 2*pos (values < 2^31, nonnegative)
    return f ? ei[2 * pos] : ei[pos];
}

// ---------------- dtype detect ----------------------------------------------
__global__ void detect_kernel(const int* __restrict__ ei) {
    if (threadIdx.x == 0 && blockIdx.x == 0) {
        d_i64 = (ei[1] == 0 && ei[3] == 0 && ei[5] == 0 && ei[7] == 0 && ei[9] == 0) ? 1 : 0;
    }
}

// ---------------- GEMM: h0 = x @ W1  (tf32 mma, split-K, cp.async pipeline) --
__global__ void __launch_bounds__(256, 1)
gemm_kernel(const float* __restrict__ x, const float* __restrict__ W1) {
    __shared__ __align__(16) float    xs[2][BM * XS_STR];
    __shared__ __align__(16) uint32_t ws[2][BK * WS_STR];

    const int tid  = threadIdx.x;
    const int lane = tid & 31;
    const int warp = tid >> 5;
    const int m0   = blockIdx.x * BM;
    const int kbeg = blockIdx.y * KCHUNK;
    const int kend = min(KD, kbeg + KCHUNK);
    const int ntile = (kend - kbeg + BK - 1) / BK;

    float acc[4][4];
#pragma unroll
    for (int a = 0; a < 4; a++)
#pragma unroll
        for (int b = 0; b < 4; b++) acc[a][b] = 0.f;

    const uint32_t xs_base = (uint32_t)__cvta_generic_to_shared(&xs[0][0]);

    auto load_tiles = [&](int buf, int kb) {
        // W1 tile: 32 k-rows x 32 cols, convert to tf32 at load time
        {
            int kk = tid >> 3, g = tid & 7;
            int gk = kb + kk;
            float4 v = make_float4(0.f, 0.f, 0.f, 0.f);
            if (gk < KD) v = *reinterpret_cast<const float4*>(W1 + (size_t)gk * HD + g * 4);
            uint4 u;
            u.x = f2tf(v.x); u.y = f2tf(v.y); u.z = f2tf(v.z); u.w = f2tf(v.w);
            *reinterpret_cast<uint4*>(&ws[buf][kk * WS_STR + g * 4]) = u;
        }
        // x tile: 128 rows x 32 cols via 8B cp.async (x rows only 8B-aligned)
        uint32_t sb = xs_base + (uint32_t)buf * (BM * XS_STR * 4);
#pragma unroll
        for (int i = 0; i < 8; i++) {
            int f   = tid + 256 * i;      // 2048 chunks of 8B
            int row = f >> 4, g = f & 15;
            int gr  = m0 + row;
            int gc  = kb + g * 2;
            const float* src = x;
            int nb = 0;
            if (gr < NN && gc < KD) {
                src = x + (size_t)gr * KD + gc;
                nb  = min(2, KD - gc) * 4;
            }
            cp8(sb + (uint32_t)(row * XS_STR + g * 2) * 4, src, nb);
        }
    };

    load_tiles(0, kbeg);
    asm volatile("cp.async.commit_group;\n" ::: "memory");

    for (int it = 0; it < ntile; it++) {
        if (it + 1 < ntile) {
            load_tiles((it + 1) & 1, kbeg + (it + 1) * BK);
            asm volatile("cp.async.commit_group;\n" ::: "memory");
            asm volatile("cp.async.wait_group 1;\n" ::: "memory");
        } else {
            asm volatile("cp.async.wait_group 0;\n" ::: "memory");
        }
        __syncthreads();

        const float*    xb = xs[it & 1];
        const uint32_t* wb = ws[it & 1];
        const int arow = warp * 16 + (lane >> 2);
        const int kq   = lane & 3;
#pragma unroll
        for (int s = 0; s < 4; s++) {
            int k8 = s * 8;
            uint32_t a0 = f2tf(xb[arow * XS_STR + k8 + kq]);
            uint32_t a1 = f2tf(xb[(arow + 8) * XS_STR + k8 + kq]);
            uint32_t a2 = f2tf(xb[arow * XS_STR + k8 + 4 + kq]);
            uint32_t a3 = f2tf(xb[(arow + 8) * XS_STR + k8 + 4 + kq]);
#pragma unroll
            for (int nt = 0; nt < 4; nt++) {
                uint32_t b0 = wb[(k8 + kq) * WS_STR + nt * 8 + (lane >> 2)];
                uint32_t b1 = wb[(k8 + 4 + kq) * WS_STR + nt * 8 + (lane >> 2)];
                asm volatile(
                    "mma.sync.aligned.m16n8k8.row.col.f32.tf32.tf32.f32 "
                    "{%0,%1,%2,%3}, {%4,%5,%6,%7}, {%8,%9}, {%0,%1,%2,%3};\n"
                    : "+f"(acc[nt][0]), "+f"(acc[nt][1]), "+f"(acc[nt][2]), "+f"(acc[nt][3])
                    : "r"(a0), "r"(a1), "r"(a2), "r"(a3), "r"(b0), "r"(b1));
            }
        }
        __syncthreads();
    }

    const int r0 = m0 + warp * 16 + (lane >> 2);
    const int r1 = r0 + 8;
    const int c0 = (lane & 3) * 2;
#pragma unroll
    for (int nt = 0; nt < 4; nt++) {
        int c = nt * 8 + c0;
        if (r0 < NN) {
            atomicAdd(&d_h0[r0 * HD + c],     acc[nt][0]);
            atomicAdd(&d_h0[r0 * HD + c + 1], acc[nt][1]);
        }
        if (r1 < NN) {
            atomicAdd(&d_h0[r1 * HD + c],     acc[nt][2]);
            atomicAdd(&d_h0[r1 * HD + c + 1], acc[nt][3]);
        }
    }
}

// ---------------- edge histogram --------------------------------------------
__global__ void hist_kernel(const int* __restrict__ ei) {
    int idx = blockIdx.x * 256 + threadIdx.x;
    if (idx >= TT * EE) return;
    int f = d_i64;
    int t = idx / EE, e = idx - t * EE;
    int j = ld_idx(ei, t * 2 * EE + EE + e, f);
    atomicAdd(&d_cnt[t * NN + j], 1);
}

// ---------------- per-t exclusive prefix scan --------------------------------
__global__ void __launch_bounds__(1024) scan_kernel() {
    int t = blockIdx.x;
    __shared__ int sb[1024];
    int base = 0;
    for (int c0 = 0; c0 < NN; c0 += 1024) {
        int i = c0 + threadIdx.x;
        int v = (i < NN) ? d_cnt[t * NN + i] : 0;
        sb[threadIdx.x] = v;
        __syncthreads();
        for (int d = 1; d < 1024; d <<= 1) {
            int add = (threadIdx.x >= (unsigned)d) ? sb[threadIdx.x - d] : 0;
            __syncthreads();
            sb[threadIdx.x] += add;
            __syncthreads();
        }
        if (i < NN) {
            int excl = base + sb[threadIdx.x] - v;
            d_off[t * (NN + 1) + i] = excl;
            d_cur[t * NN + i]       = excl;
        }
        base += sb[1023];
        __syncthreads();
    }
    if (threadIdx.x == 0) d_off[t * (NN + 1) + NN] = base;
}

// ---------------- scatter edges into CSR (grouped by dst column) -------------
__global__ void scatter_kernel(const int* __restrict__ ei, const float* __restrict__ ew) {
    int idx = blockIdx.x * 256 + threadIdx.x;
    if (idx >= TT * EE) return;
    int f = d_i64;
    int t = idx / EE, e = idx - t * EE;
    int i = ld_idx(ei, t * 2 * EE + e, f);
    int j = ld_idx(ei, t * 2 * EE + EE + e, f);
    int pos = atomicAdd(&d_cur[t * NN + j], 1);
    d_srcb[t * EE + pos] = i;
    d_eidb[t * EE + pos] = e;
    d_wb[t * EE + pos]   = ew[idx];
}

// ---------------- dedup (last edge index wins) + degrees ---------------------
__global__ void __launch_bounds__(256) dedup_kernel() {
    int gw   = (blockIdx.x * 256 + threadIdx.x) >> 5;
    int lane = threadIdx.x & 31;
    if (gw >= TT * NN) return;
    int t = gw / NN, j = gw - t * NN;
    int beg = d_off[t * (NN + 1) + j];
    int end = d_off[t * (NN + 1) + j + 1];

    float sum = 0.f;
    int selfw = 0;
    for (int p = beg + lane; p < end; p += 32) {
        int src = d_srcb[t * EE + p];
        int eid = d_eidb[t * EE + p];
        bool win = true;
        for (int q = beg; q < end; q++) {
            if (d_srcb[t * EE + q] == src && d_eidb[t * EE + q] > eid) { win = false; break; }
        }
        if (win) {
            sum += d_wb[t * EE + p];
            if (src == j) selfw = 1;
        } else {
            d_wb[t * EE + p] = 0.f;   // losers contribute nothing anywhere
        }
    }
#pragma unroll
    for (int o = 16; o; o >>= 1) {
        sum   += __shfl_xor_sync(0xffffffffu, sum, o);
        selfw |= __shfl_xor_sync(0xffffffffu, selfw, o);
    }
    if (lane == 0) {
        float diag = selfw ? 0.f : 1.f;      // self-edge winner replaces eye diagonal
        d_diag[t * NN + j] = diag;
        d_dinv[t * NN + j] = rsqrtf(diag + sum);
    }
}

// ---------------- SpMM1 + ReLU + (h @ W2) ------------------------------------
__global__ void __launch_bounds__(256) spmm1_kernel(const float* __restrict__ b1,
                                                    const float* __restrict__ W2) {
    __shared__ float hs[8][HD];
    int gw   = (blockIdx.x * 256 + threadIdx.x) >> 5;
    int lane = threadIdx.x & 31;
    int wib  = (threadIdx.x >> 5);
    if (gw >= TT * NN) return;
    int t = gw / NN, j = gw - t * NN;
    int beg = d_off[t * (NN + 1) + j];
    int end = d_off[t * (NN + 1) + j + 1];

    float dj  = d_dinv[t * NN + j];
    float acc = d_diag[t * NN + j] * dj * d_h0[j * HD + lane];
    for (int p = beg; p < end; p++) {
        int   src = d_srcb[t * EE + p];
        float w   = d_wb[t * EE + p];
        acc = fmaf(w * d_dinv[t * NN + src], d_h0[src * HD + lane], acc);
    }
    float h = fmaxf(fmaf(acc, dj, b1[lane]), 0.f);
    hs[wib][lane] = h;
    __syncwarp();
    if (lane < ZD) {
        float s = 0.f;
#pragma unroll
        for (int c = 0; c < HD; c++) s = fmaf(hs[wib][c], W2[c * ZD + lane], s);
        d_g[(size_t)gw * ZD + lane] = s;
    }
}

// ---------------- SpMM2 + tanh -> out (2 nodes per warp) ---------------------
__global__ void __launch_bounds__(256) spmm2_kernel(const float* __restrict__ b2,
                                                    float* __restrict__ out) {
    int gwarp = (blockIdx.x * 256 + threadIdx.x) >> 5;
    int lane  = threadIdx.x & 31;
    int half  = lane >> 4, k = lane & 15;
    int node  = gwarp * 2 + half;
    if (node >= TT * NN) return;
    int t = node / NN, j = node - t * NN;
    int beg = d_off[t * (NN + 1) + j];
    int end = d_off[t * (NN + 1) + j + 1];

    float dj  = d_dinv[t * NN + j];
    float acc = d_diag[t * NN + j] * dj * d_g[(size_t)node * ZD + k];
    for (int p = beg; p < end; p++) {
        int   src = d_srcb[t * EE + p];
        float w   = d_wb[t * EE + p];
        acc = fmaf(w * d_dinv[t * NN + src], d_g[(size_t)(t * NN + src) * ZD + k], acc);
    }
    out[(size_t)node * ZD + k] = tanhf(fmaf(acc, dj, b2[k]));
}

// ---------------- launch -----------------------------------------------------
extern "C" void kernel_launch(void* const* d_in, const int* in_sizes, int n_in,
                              void* d_out, int out_size) {
    const float* x  = (const float*)d_in[0];
    const int*   ei = (const int*)d_in[1];   // int32 or int64 (detected)
    const float* ew = (const float*)d_in[2];
    const float* W1 = (const float*)d_in[3];
    const float* b1 = (const float*)d_in[4];
    const float* W2 = (const float*)d_in[5];
    const float* b2 = (const float*)d_in[6];
    float* out = (float*)d_out;

    void *ph0 = nullptr, *pcnt = nullptr;
    cudaGetSymbolAddress(&ph0, d_h0);
    cudaGetSymbolAddress(&pcnt, d_cnt);
    cudaMemsetAsync(ph0, 0, sizeof(float) * NN * HD);
    cudaMemsetAsync(pcnt, 0, sizeof(int) * TT * NN);

    detect_kernel<<<1, 32>>>(ei);
    gemm_kernel<<<dim3((NN + BM - 1) / BM, KSPLIT), 256>>>(x, W1);
    hist_kernel<<<(TT * EE + 255) / 256, 256>>>(ei);
    scan_kernel<<<TT, 1024>>>();
    scatter_kernel<<<(TT * EE + 255) / 256, 256>>>(ei, ew);
    dedup_kernel<<<(TT * NN * 32 + 255) / 256, 256>>>();
    spmm1_kernel<<<(TT * NN * 32 + 255) / 256, 256>>>(b1, W2);
    spmm2_kernel<<<(TT * NN * 16 + 255) / 256, 256>>>(b2, out);
}